// round 1
// baseline (speedup 1.0000x reference)
#include <cuda_runtime.h>
#include <cstdint>
#include <cstddef>

#define IN_F   1024
#define OUT_F  1024
#define BATCH  8192
#define NFEAT  7               // silu + 6 spline bases
#define KTOT   (IN_F * NFEAT)  // 7168

// Scratch (static device arrays: allowed; no cudaMalloc anywhere)
__device__ float g_A[(size_t)KTOT * BATCH];   // features, layout [k][b], k = i*7 + j
__device__ float g_W[(size_t)KTOT * OUT_F];   // combined weights, layout [k][o]

// ---------------------------------------------------------------------------
// PTX helpers
// ---------------------------------------------------------------------------
__device__ __forceinline__ unsigned smem_u32(const void* p) {
    return (unsigned)__cvta_generic_to_shared(p);
}
#define CP_ASYNC16(dst_u32, src_ptr) \
    asm volatile("cp.async.cg.shared.global [%0], [%1], 16;\n" :: "r"(dst_u32), "l"(src_ptr))
#define CP_COMMIT() asm volatile("cp.async.commit_group;\n")
#define CP_WAIT(n)  asm volatile("cp.async.wait_group %0;\n" :: "n"(n))

#define PACK_DUP(d, s) \
    asm("mov.b64 %0, {%1, %1};" : "=l"(d) : "f"(s))
#define FMA_F32X2(acc, a, b) \
    asm("fma.rn.f32x2 %0, %1, %2, %0;" : "+l"(acc) : "l"(a), "l"(b))
#define UNPACK_2F(lo, hi, v) \
    asm("mov.b64 {%0, %1}, %2;" : "=f"(lo), "=f"(hi) : "l"(v))

// ---------------------------------------------------------------------------
// Kernel 1: combined weight  W_c[(i*7+j)*OUT_F + o]
//   j=0 : base_weight[o,i]
//   j=1+n : spline_weight[o,i,n] * spline_scaler[o,i]
// ---------------------------------------------------------------------------
__global__ void kan_prep_w(const float* __restrict__ bw,
                           const float* __restrict__ sw,
                           const float* __restrict__ sc) {
    int i = blockIdx.x;                      // 0..1023
#pragma unroll
    for (int oo = 0; oo < OUT_F / 256; oo++) {
        int o = oo * 256 + threadIdx.x;
        size_t oi = (size_t)o * IN_F + i;
        float s = sc[oi];
        float b = bw[oi];
        const float* swp = sw + oi * 6;
        size_t wbase = (size_t)(i * NFEAT) * OUT_F + o;
        g_W[wbase] = b;
#pragma unroll
        for (int n = 0; n < 6; n++)
            g_W[wbase + (size_t)(n + 1) * OUT_F] = swp[n] * s;
    }
}

// ---------------------------------------------------------------------------
// Kernel 2: feature expansion  A[(i*7+j)*BATCH + b]
// Uniform-grid closed-form cubic B-spline: for x in [-1,1):
//   u = (x+1)*1.5, idx = floor(u) in {0,1,2}, t = u - idx
//   nonzero bases at positions idx..idx+3:
//     (1-t)^3/6, (3t^3-6t^2+4)/6, (-3t^3+3t^2+3t+1)/6, t^3/6
// ---------------------------------------------------------------------------
__global__ void kan_features(const float* __restrict__ x) {
    __shared__ float sx[32][33];
    int b0 = blockIdx.x * 32;
    int i0 = blockIdx.y * 32;
    int tid = threadIdx.x;

    // coalesced load of x tile [32 b][32 i]
    int r  = tid >> 3;
    int c4 = (tid & 7) << 2;
    float4 v = *(const float4*)(x + (size_t)(b0 + r) * IN_F + i0 + c4);
    sx[r][c4 + 0] = v.x; sx[r][c4 + 1] = v.y;
    sx[r][c4 + 2] = v.z; sx[r][c4 + 3] = v.w;
    __syncthreads();

    int bl = tid & 31;
#pragma unroll
    for (int p = 0; p < 4; p++) {
        int il = p * 8 + (tid >> 5);
        float xv = sx[bl][il];

        // silu
        float e   = __expf(-xv);
        float sil = xv * __fdividef(1.0f, 1.0f + e);

        // closed-form uniform cubic B-spline
        float u  = (xv + 1.0f) * 1.5f;
        int idx  = (int)floorf(u);
        idx = idx < 0 ? 0 : (idx > 2 ? 2 : idx);
        float t  = u - (float)idx;
        float t2 = t * t, t3 = t2 * t;
        float omt = 1.0f - t;
        const float c6 = 1.0f / 6.0f;
        float v0 = omt * omt * omt * c6;
        float v1 = (3.0f * t3 - 6.0f * t2 + 4.0f) * c6;
        float v2 = (-3.0f * t3 + 3.0f * t2 + 3.0f * t + 1.0f) * c6;
        float v3 = t3 * c6;

        // scatter 4 nonzero values to 6 basis slots, branchless
        float f0 = (idx == 0) ? v0 : 0.0f;
        float f1 = (idx == 0) ? v1 : ((idx == 1) ? v0 : 0.0f);
        float f2 = (idx == 0) ? v2 : ((idx == 1) ? v1 : v0);
        float f3 = (idx == 0) ? v3 : ((idx == 1) ? v2 : v1);
        float f4 = (idx == 1) ? v3 : ((idx == 2) ? v2 : 0.0f);
        float f5 = (idx == 2) ? v3 : 0.0f;

        size_t base = (size_t)((i0 + il) * NFEAT) * BATCH + b0 + bl;
        g_A[base + 0 * BATCH] = sil;
        g_A[base + 1 * BATCH] = f0;
        g_A[base + 2 * BATCH] = f1;
        g_A[base + 3 * BATCH] = f2;
        g_A[base + 4 * BATCH] = f3;
        g_A[base + 5 * BATCH] = f4;
        g_A[base + 6 * BATCH] = f5;
    }
}

// ---------------------------------------------------------------------------
// Kernel 3: SGEMM  C[b,o] = sum_k A[k][b] * W[k][o]
// 128x128 CTA tile, BK=16, 256 threads, 8x8 micro-tile via fma.rn.f32x2,
// cp.async double buffering.
// ---------------------------------------------------------------------------
#define BM 128
#define BN 128
#define BK 16
#define NT (KTOT / BK)   // 448

__global__ __launch_bounds__(256, 2) void kan_gemm(float* __restrict__ C) {
    __shared__ float sA[2][BK][BM];
    __shared__ float sB[2][BK][BN];

    const int tid = threadIdx.x;
    const int bm0 = blockIdx.x * BM;   // batch
    const int bn0 = blockIdx.y * BN;   // out
    const int tm  = tid >> 4;          // 0..15
    const int tn  = tid & 15;          // 0..15
    const int lr  = tid >> 5;          // 0..7 (load row)
    const int lc  = (tid & 31) << 2;   // 0..124 (load col, float4)

    const float* Abase = g_A + (size_t)lr * BATCH + bm0 + lc;
    const float* Bbase = g_W + (size_t)lr * OUT_F + bn0 + lc;

    unsigned long long acc[8][4];
#pragma unroll
    for (int m = 0; m < 8; m++)
#pragma unroll
        for (int j = 0; j < 4; j++) acc[m][j] = 0ull;

    auto issue_tile = [&](int t, int buf) {
        const float* Ap = Abase + (size_t)t * BK * BATCH;
        const float* Bp = Bbase + (size_t)t * BK * OUT_F;
        unsigned da = smem_u32(&sA[buf][lr][lc]);
        unsigned db = smem_u32(&sB[buf][lr][lc]);
        CP_ASYNC16(da,                 Ap);
        CP_ASYNC16(da + 8 * BM * 4,    Ap + 8 * BATCH);
        CP_ASYNC16(db,                 Bp);
        CP_ASYNC16(db + 8 * BN * 4,    Bp + 8 * OUT_F);
        CP_COMMIT();
    };

    issue_tile(0, 0);

    for (int t = 0; t < NT; t++) {
        const int cur = t & 1;
        if (t + 1 < NT) {
            issue_tile(t + 1, cur ^ 1);
            CP_WAIT(1);
        } else {
            CP_WAIT(0);
        }
        __syncthreads();

#pragma unroll
        for (int kk = 0; kk < BK; kk++) {
            const float* ar = &sA[cur][kk][tm << 3];
            float4 a0 = *(const float4*)(ar);
            float4 a1 = *(const float4*)(ar + 4);
            const float* br = &sB[cur][kk][tn << 3];
            ulonglong2 bv0 = *(const ulonglong2*)(br);
            ulonglong2 bv1 = *(const ulonglong2*)(br + 4);

            unsigned long long ap[8];
            PACK_DUP(ap[0], a0.x); PACK_DUP(ap[1], a0.y);
            PACK_DUP(ap[2], a0.z); PACK_DUP(ap[3], a0.w);
            PACK_DUP(ap[4], a1.x); PACK_DUP(ap[5], a1.y);
            PACK_DUP(ap[6], a1.z); PACK_DUP(ap[7], a1.w);
            unsigned long long bp[4] = {bv0.x, bv0.y, bv1.x, bv1.y};

#pragma unroll
            for (int m = 0; m < 8; m++) {
#pragma unroll
                for (int j = 0; j < 4; j++) {
                    FMA_F32X2(acc[m][j], ap[m], bp[j]);
                }
            }
        }
        __syncthreads();
    }

    // epilogue
#pragma unroll
    for (int m = 0; m < 8; m++) {
        float o[8];
#pragma unroll
        for (int j = 0; j < 4; j++) {
            UNPACK_2F(o[2 * j], o[2 * j + 1], acc[m][j]);
        }
        float* cp = C + (size_t)(bm0 + (tm << 3) + m) * OUT_F + bn0 + (tn << 3);
        *(float4*)(cp)     = make_float4(o[0], o[1], o[2], o[3]);
        *(float4*)(cp + 4) = make_float4(o[4], o[5], o[6], o[7]);
    }
}

// ---------------------------------------------------------------------------
// Launch
// Inputs (metadata order): x, base_weight, spline_weight, spline_scaler, grid
// ---------------------------------------------------------------------------
extern "C" void kernel_launch(void* const* d_in, const int* in_sizes, int n_in,
                              void* d_out, int out_size) {
    (void)in_sizes; (void)n_in; (void)out_size;
    const float* x  = (const float*)d_in[0];
    const float* bw = (const float*)d_in[1];
    const float* sw = (const float*)d_in[2];
    const float* sc = (const float*)d_in[3];
    // d_in[4] = grid (uniform by construction; closed form used instead)
    float* out = (float*)d_out;

    kan_prep_w<<<IN_F, 256>>>(bw, sw, sc);
    kan_features<<<dim3(BATCH / 32, IN_F / 32), 256>>>(x);
    kan_gemm<<<dim3(BATCH / BM, OUT_F / BN), 256>>>(out);
}

// round 4
// speedup vs baseline: 3.0881x; 3.0881x over previous
#include <cuda_runtime.h>
#include <cstdint>
#include <cstddef>

#define IN_F   1024
#define OUT_F  1024
#define BATCH  8192
#define NFEAT  7
#define KTOT   (IN_F * NFEAT)   // 7168

// ---------------------------------------------------------------------------
// Scratch: tf32-rounded fp32 operands.
// g_A: [b][k] row-major (K contiguous), k permuted within each 8-block
// g_W: [o][k] same K layout
// Permutation within k8 block: orig k -> pos (k&3)*2 + (k>>2), so that the
// mma fragment pair (c, c+4) is adjacent -> every fragment load is one LDS.64.
// ---------------------------------------------------------------------------
__device__ __align__(256) float g_A[(size_t)BATCH * KTOT];
__device__ __align__(256) float g_W[(size_t)OUT_F * KTOT];

// ---------------------------------------------------------------------------
// Helpers
// ---------------------------------------------------------------------------
__device__ __forceinline__ unsigned smem_u32(const void* p) {
    return (unsigned)__cvta_generic_to_shared(p);
}
#define CP_ASYNC16(dst_u32, src_ptr) \
    asm volatile("cp.async.cg.shared.global [%0], [%1], 16;\n" :: "r"(dst_u32), "l"(src_ptr))
#define CP_COMMIT() asm volatile("cp.async.commit_group;\n")
#define CP_WAIT(n)  asm volatile("cp.async.wait_group %0;\n" :: "n"(n))

__device__ __forceinline__ uint32_t to_tf32(float v) {
    uint32_t r;
    asm("cvt.rna.tf32.f32 %0, %1;" : "=r"(r) : "f"(v));
    return r;
}
__device__ __forceinline__ uint2 lds64(uint32_t a) {
    uint2 v;
    asm volatile("ld.shared.v2.u32 {%0, %1}, [%2];" : "=r"(v.x), "=r"(v.y) : "r"(a));
    return v;
}
#define MMA_TF32(d, a0, a1, a2, a3, b0, b1) \
    asm volatile( \
        "mma.sync.aligned.m16n8k8.row.col.f32.tf32.tf32.f32 " \
        "{%0,%1,%2,%3}, {%4,%5,%6,%7}, {%8,%9}, {%0,%1,%2,%3};" \
        : "+f"((d)[0]), "+f"((d)[1]), "+f"((d)[2]), "+f"((d)[3]) \
        : "r"(a0), "r"(a1), "r"(a2), "r"(a3), "r"(b0), "r"(b1))

// permuted local-k position within the global K axis
__device__ __forceinline__ int kperm(int k) {
    return (k & ~7) | (((k & 3) << 1) | ((k >> 2) & 1));
}

// ---------------------------------------------------------------------------
// Kernel 1: combined weights -> tf32-rounded fp32, layout [o][k] (k permuted)
// ---------------------------------------------------------------------------
__global__ void kan_prep_w(const float* __restrict__ bw,
                           const float* __restrict__ sw,
                           const float* __restrict__ sc) {
    __shared__ float sbuf[256 * NFEAT];
    int o = blockIdx.x;
    int tid = threadIdx.x;
    int i = blockIdx.y * 256 + tid;
    size_t oi = (size_t)o * IN_F + i;
    float s = sc[oi];
    float vals[NFEAT];
    vals[0] = bw[oi];
    const float* swp = sw + oi * 6;
#pragma unroll
    for (int n = 0; n < 6; n++) vals[n + 1] = swp[n] * s;
#pragma unroll
    for (int j = 0; j < NFEAT; j++)
        sbuf[kperm(tid * NFEAT + j)] = __uint_as_float(to_tf32(vals[j]));
    __syncthreads();
    float4* dst = (float4*)(g_W + (size_t)o * KTOT + (size_t)blockIdx.y * (256 * NFEAT));
    dst[tid] = ((const float4*)sbuf)[tid];
    if (tid < 448 - 256) dst[tid + 256] = ((const float4*)sbuf)[tid + 256];
}

// ---------------------------------------------------------------------------
// Kernel 2: features (silu + closed-form uniform cubic B-spline)
// -> tf32-rounded fp32, layout [b][k] (k permuted)
// ---------------------------------------------------------------------------
__global__ void kan_features(const float* __restrict__ x) {
    __shared__ float sbuf[256 * NFEAT];
    int b = blockIdx.x;
    int tid = threadIdx.x;
    int i = blockIdx.y * 256 + tid;
    float xv = x[(size_t)b * IN_F + i];

    float e   = __expf(-xv);
    float sil = xv * __fdividef(1.0f, 1.0f + e);

    float u  = (xv + 1.0f) * 1.5f;
    int idx  = (int)floorf(u);
    idx = idx < 0 ? 0 : (idx > 2 ? 2 : idx);
    float t  = u - (float)idx;
    float t2 = t * t, t3 = t2 * t;
    float omt = 1.0f - t;
    const float c6 = 1.0f / 6.0f;
    float v0 = omt * omt * omt * c6;
    float v1 = (3.0f * t3 - 6.0f * t2 + 4.0f) * c6;
    float v2 = (-3.0f * t3 + 3.0f * t2 + 3.0f * t + 1.0f) * c6;
    float v3 = t3 * c6;

    float vals[NFEAT];
    vals[0] = sil;
    vals[1] = (idx == 0) ? v0 : 0.0f;
    vals[2] = (idx == 0) ? v1 : ((idx == 1) ? v0 : 0.0f);
    vals[3] = (idx == 0) ? v2 : ((idx == 1) ? v1 : v0);
    vals[4] = (idx == 0) ? v3 : ((idx == 1) ? v2 : v1);
    vals[5] = (idx == 1) ? v3 : ((idx == 2) ? v2 : 0.0f);
    vals[6] = (idx == 2) ? v3 : 0.0f;

#pragma unroll
    for (int j = 0; j < NFEAT; j++)
        sbuf[kperm(tid * NFEAT + j)] = __uint_as_float(to_tf32(vals[j]));
    __syncthreads();
    float4* dst = (float4*)(g_A + (size_t)b * KTOT + (size_t)blockIdx.y * (256 * NFEAT));
    dst[tid] = ((const float4*)sbuf)[tid];
    if (tid < 448 - 256) dst[tid + 256] = ((const float4*)sbuf)[tid + 256];
}

// ---------------------------------------------------------------------------
// Kernel 3: tf32 mma.sync GEMM  C[b,o] = sum_k A[b][k] * W[o][k]
// CTA 128x256, BK=32, 256 threads (8 warps, 2x4 grid, warp tile 64x64),
// 3-stage cp.async ring. Smem rows padded to 160B for conflict-free LDS.64.
// ---------------------------------------------------------------------------
#define BM 128
#define BN 256
#define BK 32
#define NT (KTOT / BK)          // 224
#define LDSW 40                 // floats per smem row (160B)
#define A_STG_F (BM * LDSW)     // 5120 floats = 20KB
#define B_STG_F (BN * LDSW)     // 10240 floats = 40KB
#define STG_F (A_STG_F + B_STG_F)
#define NSTAGE 3
#define SMEM_TOTAL (NSTAGE * STG_F * 4)   // 184320 bytes

__device__ __forceinline__ void load_stage(uint32_t sb, int bm0, int bn0,
                                           int t, int stg, int tid) {
    uint32_t base = sb + stg * (STG_F * 4);
    int k0 = t * BK;
    // A: 128 rows x 8 chunks of 16B
#pragma unroll
    for (int r = 0; r < 4; r++) {
        int c = tid + r * 256;
        int row = c >> 3, ch = c & 7;
        CP_ASYNC16(base + (uint32_t)(row * (LDSW * 4) + ch * 16),
                   g_A + (size_t)(bm0 + row) * KTOT + k0 + ch * 4);
    }
    // B: 256 rows x 8 chunks
    uint32_t bbase = base + A_STG_F * 4;
#pragma unroll
    for (int r = 0; r < 8; r++) {
        int c = tid + r * 256;
        int row = c >> 3, ch = c & 7;
        CP_ASYNC16(bbase + (uint32_t)(row * (LDSW * 4) + ch * 16),
                   g_W + (size_t)(bn0 + row) * KTOT + k0 + ch * 4);
    }
    CP_COMMIT();
}

__global__ __launch_bounds__(256, 1) void kan_gemm(float* __restrict__ C) {
    extern __shared__ float dsm[];
    uint32_t sb = smem_u32(dsm);
    const int tid = threadIdx.x;
    const int wid = tid >> 5, lane = tid & 31;
    const int q = lane >> 2, cl = lane & 3;
    const int bm0 = blockIdx.x * BM;
    const int bn0 = blockIdx.y * BN;
    const int m0 = (wid & 1) * 64;    // warp M offset
    const int n0 = (wid >> 1) * 64;   // warp N offset

    float d[4][8][4];
#pragma unroll
    for (int mb = 0; mb < 4; mb++)
#pragma unroll
        for (int nb = 0; nb < 8; nb++)
#pragma unroll
            for (int r = 0; r < 4; r++) d[mb][nb][r] = 0.0f;

    load_stage(sb, bm0, bn0, 0, 0, tid);
    load_stage(sb, bm0, bn0, 1, 1, tid);

    for (int t = 0; t < NT; t++) {
        const int stg = t % NSTAGE;
        CP_WAIT(1);
        __syncthreads();
        if (t + 2 < NT) load_stage(sb, bm0, bn0, t + 2, (t + 2) % NSTAGE, tid);

        uint32_t abase = sb + stg * (STG_F * 4) + (uint32_t)((m0 + q) * (LDSW * 4) + cl * 8);
        uint32_t bbase = sb + stg * (STG_F * 4) + A_STG_F * 4
                       + (uint32_t)((n0 + q) * (LDSW * 4) + cl * 8);
#pragma unroll
        for (int kk = 0; kk < 4; kk++) {
            uint2 a[4][2];
#pragma unroll
            for (int mb = 0; mb < 4; mb++) {
                uint32_t aa = abase + (uint32_t)(mb * 16 * (LDSW * 4) + kk * 32);
                a[mb][0] = lds64(aa);
                a[mb][1] = lds64(aa + 8 * (LDSW * 4));
            }
            uint2 b[8];
#pragma unroll
            for (int nb = 0; nb < 8; nb++)
                b[nb] = lds64(bbase + (uint32_t)(nb * 8 * (LDSW * 4) + kk * 32));
#pragma unroll
            for (int mb = 0; mb < 4; mb++)
#pragma unroll
                for (int nb = 0; nb < 8; nb++)
                    MMA_TF32(d[mb][nb], a[mb][0].x, a[mb][1].x, a[mb][0].y, a[mb][1].y,
                             b[nb].x, b[nb].y);
        }
        __syncthreads();
    }

    // epilogue: direct global stores; each 4-lane group writes a contiguous 32B run
#pragma unroll
    for (int mb = 0; mb < 4; mb++) {
        int row0 = bm0 + m0 + mb * 16 + q;
#pragma unroll
        for (int nb = 0; nb < 8; nb++) {
            int col = bn0 + n0 + nb * 8 + 2 * cl;
            float2* p0 = (float2*)(C + (size_t)row0 * OUT_F + col);
            *p0 = make_float2(d[mb][nb][0], d[mb][nb][1]);
            float2* p1 = (float2*)(C + (size_t)(row0 + 8) * OUT_F + col);
            *p1 = make_float2(d[mb][nb][2], d[mb][nb][3]);
        }
    }
}

// ---------------------------------------------------------------------------
// Launch. Inputs: x, base_weight, spline_weight, spline_scaler, grid
// ---------------------------------------------------------------------------
extern "C" void kernel_launch(void* const* d_in, const int* in_sizes, int n_in,
                              void* d_out, int out_size) {
    (void)in_sizes; (void)n_in; (void)out_size;
    const float* x  = (const float*)d_in[0];
    const float* bw = (const float*)d_in[1];
    const float* sw = (const float*)d_in[2];
    const float* sc = (const float*)d_in[3];
    float* out = (float*)d_out;

    cudaFuncSetAttribute(kan_gemm, cudaFuncAttributeMaxDynamicSharedMemorySize,
                         SMEM_TOTAL);

    kan_prep_w<<<dim3(OUT_F, IN_F / 256), 256>>>(bw, sw, sc);
    kan_features<<<dim3(BATCH, IN_F / 256), 256>>>(x);
    kan_gemm<<<dim3(BATCH / BM, OUT_F / BN), 256, SMEM_TOTAL>>>(out);
}

// round 5
// speedup vs baseline: 3.0888x; 1.0002x over previous
#include <cuda_runtime.h>
#include <cstdint>
#include <cstddef>

#define IN_F   1024
#define OUT_F  1024
#define BATCH  8192
#define NFEAT  7
#define KTOT   (IN_F * NFEAT)   // 7168

// ---------------------------------------------------------------------------
// Scratch: tf32-rounded fp32 operands.
// g_A: [b][k] row-major (K contiguous), k permuted within each 8-block
// g_W: [o][k] same K layout
// Permutation within k8 block: orig k -> pos (k&3)*2 + (k>>2), so that the
// mma fragment pair (c, c+4) is adjacent -> every fragment load is one LDS.64.
// ---------------------------------------------------------------------------
__device__ __align__(256) float g_A[(size_t)BATCH * KTOT];
__device__ __align__(256) float g_W[(size_t)OUT_F * KTOT];

// ---------------------------------------------------------------------------
// Helpers
// ---------------------------------------------------------------------------
__device__ __forceinline__ unsigned smem_u32(const void* p) {
    return (unsigned)__cvta_generic_to_shared(p);
}
#define CP_ASYNC16(dst_u32, src_ptr) \
    asm volatile("cp.async.cg.shared.global [%0], [%1], 16;\n" :: "r"(dst_u32), "l"(src_ptr))
#define CP_COMMIT() asm volatile("cp.async.commit_group;\n")
#define CP_WAIT(n)  asm volatile("cp.async.wait_group %0;\n" :: "n"(n))

__device__ __forceinline__ uint32_t to_tf32(float v) {
    uint32_t r;
    asm("cvt.rna.tf32.f32 %0, %1;" : "=r"(r) : "f"(v));
    return r;
}
__device__ __forceinline__ uint2 lds64(uint32_t a) {
    uint2 v;
    asm volatile("ld.shared.v2.u32 {%0, %1}, [%2];" : "=r"(v.x), "=r"(v.y) : "r"(a));
    return v;
}
#define MMA_TF32(d, a0, a1, a2, a3, b0, b1) \
    asm volatile( \
        "mma.sync.aligned.m16n8k8.row.col.f32.tf32.tf32.f32 " \
        "{%0,%1,%2,%3}, {%4,%5,%6,%7}, {%8,%9}, {%0,%1,%2,%3};" \
        : "+f"((d)[0]), "+f"((d)[1]), "+f"((d)[2]), "+f"((d)[3]) \
        : "r"(a0), "r"(a1), "r"(a2), "r"(a3), "r"(b0), "r"(b1))

// permuted local-k position within the global K axis
__device__ __forceinline__ int kperm(int k) {
    return (k & ~7) | (((k & 3) << 1) | ((k >> 2) & 1));
}

// ---------------------------------------------------------------------------
// Kernel 1: combined weights -> tf32-rounded fp32, layout [o][k] (k permuted)
// ---------------------------------------------------------------------------
__global__ void kan_prep_w(const float* __restrict__ bw,
                           const float* __restrict__ sw,
                           const float* __restrict__ sc) {
    __shared__ float sbuf[256 * NFEAT];
    int o = blockIdx.x;
    int tid = threadIdx.x;
    int i = blockIdx.y * 256 + tid;
    size_t oi = (size_t)o * IN_F + i;
    float s = sc[oi];
    float vals[NFEAT];
    vals[0] = bw[oi];
    const float* swp = sw + oi * 6;
#pragma unroll
    for (int n = 0; n < 6; n++) vals[n + 1] = swp[n] * s;
#pragma unroll
    for (int j = 0; j < NFEAT; j++)
        sbuf[kperm(tid * NFEAT + j)] = __uint_as_float(to_tf32(vals[j]));
    __syncthreads();
    float4* dst = (float4*)(g_W + (size_t)o * KTOT + (size_t)blockIdx.y * (256 * NFEAT));
    dst[tid] = ((const float4*)sbuf)[tid];
    if (tid < 448 - 256) dst[tid + 256] = ((const float4*)sbuf)[tid + 256];
}

// ---------------------------------------------------------------------------
// Kernel 2: features (silu + closed-form uniform cubic B-spline)
// -> tf32-rounded fp32, layout [b][k] (k permuted)
// ---------------------------------------------------------------------------
__global__ void kan_features(const float* __restrict__ x) {
    __shared__ float sbuf[256 * NFEAT];
    int b = blockIdx.x;
    int tid = threadIdx.x;
    int i = blockIdx.y * 256 + tid;
    float xv = x[(size_t)b * IN_F + i];

    float e   = __expf(-xv);
    float sil = xv * __fdividef(1.0f, 1.0f + e);

    float u  = (xv + 1.0f) * 1.5f;
    int idx  = (int)floorf(u);
    idx = idx < 0 ? 0 : (idx > 2 ? 2 : idx);
    float t  = u - (float)idx;
    float t2 = t * t, t3 = t2 * t;
    float omt = 1.0f - t;
    const float c6 = 1.0f / 6.0f;
    float v0 = omt * omt * omt * c6;
    float v1 = (3.0f * t3 - 6.0f * t2 + 4.0f) * c6;
    float v2 = (-3.0f * t3 + 3.0f * t2 + 3.0f * t + 1.0f) * c6;
    float v3 = t3 * c6;

    float vals[NFEAT];
    vals[0] = sil;
    vals[1] = (idx == 0) ? v0 : 0.0f;
    vals[2] = (idx == 0) ? v1 : ((idx == 1) ? v0 : 0.0f);
    vals[3] = (idx == 0) ? v2 : ((idx == 1) ? v1 : v0);
    vals[4] = (idx == 0) ? v3 : ((idx == 1) ? v2 : v1);
    vals[5] = (idx == 1) ? v3 : ((idx == 2) ? v2 : 0.0f);
    vals[6] = (idx == 2) ? v3 : 0.0f;

#pragma unroll
    for (int j = 0; j < NFEAT; j++)
        sbuf[kperm(tid * NFEAT + j)] = __uint_as_float(to_tf32(vals[j]));
    __syncthreads();
    float4* dst = (float4*)(g_A + (size_t)b * KTOT + (size_t)blockIdx.y * (256 * NFEAT));
    dst[tid] = ((const float4*)sbuf)[tid];
    if (tid < 448 - 256) dst[tid + 256] = ((const float4*)sbuf)[tid + 256];
}

// ---------------------------------------------------------------------------
// Kernel 3: tf32 mma.sync GEMM  C[b,o] = sum_k A[b][k] * W[o][k]
// CTA 128x256, BK=32, 256 threads (8 warps, 2x4 grid, warp tile 64x64),
// 3-stage cp.async ring. Smem rows padded to 160B for conflict-free LDS.64.
// ---------------------------------------------------------------------------
#define BM 128
#define BN 256
#define BK 32
#define NT (KTOT / BK)          // 224
#define LDSW 40                 // floats per smem row (160B)
#define A_STG_F (BM * LDSW)     // 5120 floats = 20KB
#define B_STG_F (BN * LDSW)     // 10240 floats = 40KB
#define STG_F (A_STG_F + B_STG_F)
#define NSTAGE 3
#define SMEM_TOTAL (NSTAGE * STG_F * 4)   // 184320 bytes

__device__ __forceinline__ void load_stage(uint32_t sb, int bm0, int bn0,
                                           int t, int stg, int tid) {
    uint32_t base = sb + stg * (STG_F * 4);
    int k0 = t * BK;
    // A: 128 rows x 8 chunks of 16B
#pragma unroll
    for (int r = 0; r < 4; r++) {
        int c = tid + r * 256;
        int row = c >> 3, ch = c & 7;
        CP_ASYNC16(base + (uint32_t)(row * (LDSW * 4) + ch * 16),
                   g_A + (size_t)(bm0 + row) * KTOT + k0 + ch * 4);
    }
    // B: 256 rows x 8 chunks
    uint32_t bbase = base + A_STG_F * 4;
#pragma unroll
    for (int r = 0; r < 8; r++) {
        int c = tid + r * 256;
        int row = c >> 3, ch = c & 7;
        CP_ASYNC16(bbase + (uint32_t)(row * (LDSW * 4) + ch * 16),
                   g_W + (size_t)(bn0 + row) * KTOT + k0 + ch * 4);
    }
    CP_COMMIT();
}

__global__ __launch_bounds__(256, 1) void kan_gemm(float* __restrict__ C) {
    extern __shared__ float dsm[];
    uint32_t sb = smem_u32(dsm);
    const int tid = threadIdx.x;
    const int wid = tid >> 5, lane = tid & 31;
    const int q = lane >> 2, cl = lane & 3;
    const int bm0 = blockIdx.x * BM;
    const int bn0 = blockIdx.y * BN;
    const int m0 = (wid & 1) * 64;    // warp M offset
    const int n0 = (wid >> 1) * 64;   // warp N offset

    float d[4][8][4];
#pragma unroll
    for (int mb = 0; mb < 4; mb++)
#pragma unroll
        for (int nb = 0; nb < 8; nb++)
#pragma unroll
            for (int r = 0; r < 4; r++) d[mb][nb][r] = 0.0f;

    load_stage(sb, bm0, bn0, 0, 0, tid);
    load_stage(sb, bm0, bn0, 1, 1, tid);

    for (int t = 0; t < NT; t++) {
        const int stg = t % NSTAGE;
        CP_WAIT(1);
        __syncthreads();
        if (t + 2 < NT) load_stage(sb, bm0, bn0, t + 2, (t + 2) % NSTAGE, tid);

        uint32_t abase = sb + stg * (STG_F * 4) + (uint32_t)((m0 + q) * (LDSW * 4) + cl * 8);
        uint32_t bbase = sb + stg * (STG_F * 4) + A_STG_F * 4
                       + (uint32_t)((n0 + q) * (LDSW * 4) + cl * 8);
#pragma unroll
        for (int kk = 0; kk < 4; kk++) {
            uint2 a[4][2];
#pragma unroll
            for (int mb = 0; mb < 4; mb++) {
                uint32_t aa = abase + (uint32_t)(mb * 16 * (LDSW * 4) + kk * 32);
                a[mb][0] = lds64(aa);
                a[mb][1] = lds64(aa + 8 * (LDSW * 4));
            }
            uint2 b[8];
#pragma unroll
            for (int nb = 0; nb < 8; nb++)
                b[nb] = lds64(bbase + (uint32_t)(nb * 8 * (LDSW * 4) + kk * 32));
#pragma unroll
            for (int mb = 0; mb < 4; mb++)
#pragma unroll
                for (int nb = 0; nb < 8; nb++)
                    MMA_TF32(d[mb][nb], a[mb][0].x, a[mb][1].x, a[mb][0].y, a[mb][1].y,
                             b[nb].x, b[nb].y);
        }
        __syncthreads();
    }

    // epilogue: direct global stores; each 4-lane group writes a contiguous 32B run
#pragma unroll
    for (int mb = 0; mb < 4; mb++) {
        int row0 = bm0 + m0 + mb * 16 + q;
#pragma unroll
        for (int nb = 0; nb < 8; nb++) {
            int col = bn0 + n0 + nb * 8 + 2 * cl;
            float2* p0 = (float2*)(C + (size_t)row0 * OUT_F + col);
            *p0 = make_float2(d[mb][nb][0], d[mb][nb][1]);
            float2* p1 = (float2*)(C + (size_t)(row0 + 8) * OUT_F + col);
            *p1 = make_float2(d[mb][nb][2], d[mb][nb][3]);
        }
    }
}

// ---------------------------------------------------------------------------
// Launch. Inputs: x, base_weight, spline_weight, spline_scaler, grid
// ---------------------------------------------------------------------------
extern "C" void kernel_launch(void* const* d_in, const int* in_sizes, int n_in,
                              void* d_out, int out_size) {
    (void)in_sizes; (void)n_in; (void)out_size;
    const float* x  = (const float*)d_in[0];
    const float* bw = (const float*)d_in[1];
    const float* sw = (const float*)d_in[2];
    const float* sc = (const float*)d_in[3];
    float* out = (float*)d_out;

    cudaFuncSetAttribute(kan_gemm, cudaFuncAttributeMaxDynamicSharedMemorySize,
                         SMEM_TOTAL);

    kan_prep_w<<<dim3(OUT_F, IN_F / 256), 256>>>(bw, sw, sc);
    kan_features<<<dim3(BATCH, IN_F / 256), 256>>>(x);
    kan_gemm<<<dim3(BATCH / BM, OUT_F / BN), 256, SMEM_TOTAL>>>(out);
}

// round 6
// speedup vs baseline: 3.1394x; 1.0164x over previous
#include <cuda_runtime.h>
#include <cstdint>
#include <cstddef>

#define IN_F   1024
#define OUT_F  1024
#define BATCH  8192
#define NFEAT  7
#define KTOT   (IN_F * NFEAT)   // 7168

// ---------------------------------------------------------------------------
// Scratch: tf32-rounded fp32 operands.
// g_A: [b][k] row-major (K contiguous), k permuted within each 8-block
// g_W: [o][k] same K layout
// Permutation within k8 block: orig k -> pos (k&3)*2 + (k>>2), so that the
// mma fragment pair (c, c+4) is adjacent -> every fragment load is one LDS.64.
// ---------------------------------------------------------------------------
__device__ __align__(256) float g_A[(size_t)BATCH * KTOT];
__device__ __align__(256) float g_W[(size_t)OUT_F * KTOT];

// ---------------------------------------------------------------------------
// Helpers
// ---------------------------------------------------------------------------
__device__ __forceinline__ unsigned smem_u32(const void* p) {
    return (unsigned)__cvta_generic_to_shared(p);
}
#define CP_ASYNC16(dst_u32, src_ptr) \
    asm volatile("cp.async.cg.shared.global [%0], [%1], 16;\n" :: "r"(dst_u32), "l"(src_ptr))
#define CP_COMMIT() asm volatile("cp.async.commit_group;\n")
#define CP_WAIT(n)  asm volatile("cp.async.wait_group %0;\n" :: "n"(n))

__device__ __forceinline__ uint32_t to_tf32(float v) {
    uint32_t r;
    asm("cvt.rna.tf32.f32 %0, %1;" : "=r"(r) : "f"(v));
    return r;
}
__device__ __forceinline__ uint2 lds64(uint32_t a) {
    uint2 v;
    asm volatile("ld.shared.v2.u32 {%0, %1}, [%2];" : "=r"(v.x), "=r"(v.y) : "r"(a));
    return v;
}
#define MMA_TF32(d, a0, a1, a2, a3, b0, b1) \
    asm volatile( \
        "mma.sync.aligned.m16n8k8.row.col.f32.tf32.tf32.f32 " \
        "{%0,%1,%2,%3}, {%4,%5,%6,%7}, {%8,%9}, {%0,%1,%2,%3};" \
        : "+f"((d)[0]), "+f"((d)[1]), "+f"((d)[2]), "+f"((d)[3]) \
        : "r"(a0), "r"(a1), "r"(a2), "r"(a3), "r"(b0), "r"(b1))

// permuted local-k position within the global K axis
__device__ __forceinline__ int kperm(int k) {
    return (k & ~7) | (((k & 3) << 1) | ((k >> 2) & 1));
}

// ---------------------------------------------------------------------------
// Kernel 1: combined weights -> tf32-rounded fp32, layout [o][k] (k permuted)
// ---------------------------------------------------------------------------
__global__ void kan_prep_w(const float* __restrict__ bw,
                           const float* __restrict__ sw,
                           const float* __restrict__ sc) {
    __shared__ float sbuf[256 * NFEAT];
    int o = blockIdx.x;
    int tid = threadIdx.x;
    int i = blockIdx.y * 256 + tid;
    size_t oi = (size_t)o * IN_F + i;
    float s = sc[oi];
    float vals[NFEAT];
    vals[0] = bw[oi];
    const float* swp = sw + oi * 6;
#pragma unroll
    for (int n = 0; n < 6; n++) vals[n + 1] = swp[n] * s;
#pragma unroll
    for (int j = 0; j < NFEAT; j++)
        sbuf[kperm(tid * NFEAT + j)] = __uint_as_float(to_tf32(vals[j]));
    __syncthreads();
    float4* dst = (float4*)(g_W + (size_t)o * KTOT + (size_t)blockIdx.y * (256 * NFEAT));
    dst[tid] = ((const float4*)sbuf)[tid];
    if (tid < 448 - 256) dst[tid + 256] = ((const float4*)sbuf)[tid + 256];
}

// ---------------------------------------------------------------------------
// Kernel 2: features (silu + closed-form uniform cubic B-spline)
// -> tf32-rounded fp32, layout [b][k] (k permuted)
// ---------------------------------------------------------------------------
__global__ void kan_features(const float* __restrict__ x) {
    __shared__ float sbuf[256 * NFEAT];
    int b = blockIdx.x;
    int tid = threadIdx.x;
    int i = blockIdx.y * 256 + tid;
    float xv = x[(size_t)b * IN_F + i];

    float e   = __expf(-xv);
    float sil = xv * __fdividef(1.0f, 1.0f + e);

    float u  = (xv + 1.0f) * 1.5f;
    int idx  = (int)floorf(u);
    idx = idx < 0 ? 0 : (idx > 2 ? 2 : idx);
    float t  = u - (float)idx;
    float t2 = t * t, t3 = t2 * t;
    float omt = 1.0f - t;
    const float c6 = 1.0f / 6.0f;
    float v0 = omt * omt * omt * c6;
    float v1 = (3.0f * t3 - 6.0f * t2 + 4.0f) * c6;
    float v2 = (-3.0f * t3 + 3.0f * t2 + 3.0f * t + 1.0f) * c6;
    float v3 = t3 * c6;

    float vals[NFEAT];
    vals[0] = sil;
    vals[1] = (idx == 0) ? v0 : 0.0f;
    vals[2] = (idx == 0) ? v1 : ((idx == 1) ? v0 : 0.0f);
    vals[3] = (idx == 0) ? v2 : ((idx == 1) ? v1 : v0);
    vals[4] = (idx == 0) ? v3 : ((idx == 1) ? v2 : v1);
    vals[5] = (idx == 1) ? v3 : ((idx == 2) ? v2 : 0.0f);
    vals[6] = (idx == 2) ? v3 : 0.0f;

#pragma unroll
    for (int j = 0; j < NFEAT; j++)
        sbuf[kperm(tid * NFEAT + j)] = __uint_as_float(to_tf32(vals[j]));
    __syncthreads();
    float4* dst = (float4*)(g_A + (size_t)b * KTOT + (size_t)blockIdx.y * (256 * NFEAT));
    dst[tid] = ((const float4*)sbuf)[tid];
    if (tid < 448 - 256) dst[tid + 256] = ((const float4*)sbuf)[tid + 256];
}

// ---------------------------------------------------------------------------
// Kernel 3: tf32 mma.sync GEMM  C[b,o] = sum_k A[b][k] * W[o][k]
// CTA 128x256, BK=32, 256 threads (8 warps, 2x4 grid, warp tile 64x64),
// 3-stage cp.async ring, single barrier per K-tile, register-double-buffered
// fragments. Grid: x = bn (fastest) so consecutive CTAs share the A tile.
// ---------------------------------------------------------------------------
#define BM 128
#define BN 256
#define BK 32
#define NT (KTOT / BK)          // 224
#define LDSW 40                 // floats per smem row (160B)
#define A_STG_F (BM * LDSW)     // 5120 floats = 20KB
#define B_STG_F (BN * LDSW)     // 10240 floats = 40KB
#define STG_F (A_STG_F + B_STG_F)
#define NSTAGE 3
#define SMEM_TOTAL (NSTAGE * STG_F * 4)   // 184320 bytes

__device__ __forceinline__ void load_stage(uint32_t sb, int bm0, int bn0,
                                           int t, int stg, int tid) {
    uint32_t base = sb + stg * (STG_F * 4);
    int k0 = t * BK;
    // A: 128 rows x 8 chunks of 16B
#pragma unroll
    for (int r = 0; r < 4; r++) {
        int c = tid + r * 256;
        int row = c >> 3, ch = c & 7;
        CP_ASYNC16(base + (uint32_t)(row * (LDSW * 4) + ch * 16),
                   g_A + (size_t)(bm0 + row) * KTOT + k0 + ch * 4);
    }
    // B: 256 rows x 8 chunks
    uint32_t bbase = base + A_STG_F * 4;
#pragma unroll
    for (int r = 0; r < 8; r++) {
        int c = tid + r * 256;
        int row = c >> 3, ch = c & 7;
        CP_ASYNC16(bbase + (uint32_t)(row * (LDSW * 4) + ch * 16),
                   g_W + (size_t)(bn0 + row) * KTOT + k0 + ch * 4);
    }
    CP_COMMIT();
}

struct Frag {
    uint2 a[4][2];
    uint2 b[8];
};

__device__ __forceinline__ void load_frag(Frag& f, uint32_t abase, uint32_t bbase,
                                          int kk) {
#pragma unroll
    for (int mb = 0; mb < 4; mb++) {
        uint32_t aa = abase + (uint32_t)(mb * 16 * (LDSW * 4) + kk * 32);
        f.a[mb][0] = lds64(aa);
        f.a[mb][1] = lds64(aa + 8 * (LDSW * 4));
    }
#pragma unroll
    for (int nb = 0; nb < 8; nb++)
        f.b[nb] = lds64(bbase + (uint32_t)(nb * 8 * (LDSW * 4) + kk * 32));
}

__global__ __launch_bounds__(256, 1) void kan_gemm(float* __restrict__ C) {
    extern __shared__ float dsm[];
    uint32_t sb = smem_u32(dsm);
    const int tid = threadIdx.x;
    const int wid = tid >> 5, lane = tid & 31;
    const int q = lane >> 2, cl = lane & 3;
    const int bm0 = blockIdx.y * BM;   // y = bm (slow)
    const int bn0 = blockIdx.x * BN;   // x = bn (fast): consecutive CTAs share A
    const int m0 = (wid & 1) * 64;
    const int n0 = (wid >> 1) * 64;

    float d[4][8][4];
#pragma unroll
    for (int mb = 0; mb < 4; mb++)
#pragma unroll
        for (int nb = 0; nb < 8; nb++)
#pragma unroll
            for (int r = 0; r < 4; r++) d[mb][nb][r] = 0.0f;

    load_stage(sb, bm0, bn0, 0, 0, tid);
    load_stage(sb, bm0, bn0, 1, 1, tid);

    const uint32_t afoff = (uint32_t)((m0 + q) * (LDSW * 4) + cl * 8);
    const uint32_t bfoff = (uint32_t)(A_STG_F * 4 + (n0 + q) * (LDSW * 4) + cl * 8);

    Frag fr[2];
    for (int t = 0; t < NT; t++) {
        const int stg = t % NSTAGE;
        CP_WAIT(1);
        __syncthreads();
        if (t + 2 < NT) load_stage(sb, bm0, bn0, t + 2, (t + 2) % NSTAGE, tid);

        const uint32_t stbase = sb + stg * (STG_F * 4);
        const uint32_t abase = stbase + afoff;
        const uint32_t bbase = stbase + bfoff;

        load_frag(fr[0], abase, bbase, 0);
#pragma unroll
        for (int kk = 0; kk < 4; kk++) {
            if (kk < 3) load_frag(fr[(kk + 1) & 1], abase, bbase, kk + 1);
            Frag& f = fr[kk & 1];
#pragma unroll
            for (int mb = 0; mb < 4; mb++)
#pragma unroll
                for (int nb = 0; nb < 8; nb++)
                    MMA_TF32(d[mb][nb], f.a[mb][0].x, f.a[mb][1].x,
                             f.a[mb][0].y, f.a[mb][1].y, f.b[nb].x, f.b[nb].y);
        }
        // no trailing barrier: the next iteration's top barrier protects the
        // stage that will be refilled (prefetch distance 2, 3-stage ring).
    }

    // epilogue: each 4-lane group writes contiguous float2 runs
#pragma unroll
    for (int mb = 0; mb < 4; mb++) {
        int row0 = bm0 + m0 + mb * 16 + q;
#pragma unroll
        for (int nb = 0; nb < 8; nb++) {
            int col = bn0 + n0 + nb * 8 + 2 * cl;
            float2* p0 = (float2*)(C + (size_t)row0 * OUT_F + col);
            *p0 = make_float2(d[mb][nb][0], d[mb][nb][1]);
            float2* p1 = (float2*)(C + (size_t)(row0 + 8) * OUT_F + col);
            *p1 = make_float2(d[mb][nb][2], d[mb][nb][3]);
        }
    }
}

// ---------------------------------------------------------------------------
// Launch. Inputs: x, base_weight, spline_weight, spline_scaler, grid
// ---------------------------------------------------------------------------
extern "C" void kernel_launch(void* const* d_in, const int* in_sizes, int n_in,
                              void* d_out, int out_size) {
    (void)in_sizes; (void)n_in; (void)out_size;
    const float* x  = (const float*)d_in[0];
    const float* bw = (const float*)d_in[1];
    const float* sw = (const float*)d_in[2];
    const float* sc = (const float*)d_in[3];
    float* out = (float*)d_out;

    cudaFuncSetAttribute(kan_gemm, cudaFuncAttributeMaxDynamicSharedMemorySize,
                         SMEM_TOTAL);

    kan_prep_w<<<dim3(OUT_F, IN_F / 256), 256>>>(bw, sw, sc);
    kan_features<<<dim3(BATCH, IN_F / 256), 256>>>(x);
    kan_gemm<<<dim3(OUT_F / BN, BATCH / BM), 256, SMEM_TOTAL>>>(out);
}

// round 7
// speedup vs baseline: 5.5902x; 1.7807x over previous
#include <cuda_runtime.h>
#include <cuda_fp16.h>
#include <cstdint>
#include <cstddef>

#define IN_F   1024
#define OUT_F  1024
#define BATCH  8192
#define NFEAT  7
#define KTOT   (IN_F * NFEAT)   // 7168

// ---------------------------------------------------------------------------
// Scratch: fp16 operands (fp32 accumulate in the MMA).
// g_A: [b][k] row-major, natural k order. g_W: [o][k].
// ---------------------------------------------------------------------------
__device__ __align__(256) __half g_A[(size_t)BATCH * KTOT];
__device__ __align__(256) __half g_W[(size_t)OUT_F * KTOT];

// ---------------------------------------------------------------------------
// Helpers
// ---------------------------------------------------------------------------
__device__ __forceinline__ unsigned smem_u32(const void* p) {
    return (unsigned)__cvta_generic_to_shared(p);
}
#define CP_ASYNC16(dst_u32, src_ptr) \
    asm volatile("cp.async.cg.shared.global [%0], [%1], 16;\n" :: "r"(dst_u32), "l"(src_ptr))
#define CP_COMMIT() asm volatile("cp.async.commit_group;\n")
#define CP_WAIT(n)  asm volatile("cp.async.wait_group %0;\n" :: "n"(n))

__device__ __forceinline__ uint32_t lds32(uint32_t a) {
    uint32_t v;
    asm volatile("ld.shared.u32 %0, [%1];" : "=r"(v) : "r"(a));
    return v;
}
#define MMA_F16(d, a0, a1, a2, a3, b0, b1) \
    asm volatile( \
        "mma.sync.aligned.m16n8k16.row.col.f32.f16.f16.f32 " \
        "{%0,%1,%2,%3}, {%4,%5,%6,%7}, {%8,%9}, {%0,%1,%2,%3};" \
        : "+f"((d)[0]), "+f"((d)[1]), "+f"((d)[2]), "+f"((d)[3]) \
        : "r"(a0), "r"(a1), "r"(a2), "r"(a3), "r"(b0), "r"(b1))

// ---------------------------------------------------------------------------
// Kernel 1: combined weights -> fp16, layout [o][k]
// ---------------------------------------------------------------------------
__global__ void kan_prep_w(const float* __restrict__ bw,
                           const float* __restrict__ sw,
                           const float* __restrict__ sc) {
    __shared__ __half sbuf[256 * NFEAT];
    int o = blockIdx.x;
    int tid = threadIdx.x;
    int i = blockIdx.y * 256 + tid;
    size_t oi = (size_t)o * IN_F + i;
    float s = sc[oi];
    float vals[NFEAT];
    vals[0] = bw[oi];
    const float* swp = sw + oi * 6;
#pragma unroll
    for (int n = 0; n < 6; n++) vals[n + 1] = swp[n] * s;
#pragma unroll
    for (int j = 0; j < NFEAT; j++)
        sbuf[tid * NFEAT + j] = __float2half_rn(vals[j]);
    __syncthreads();
    float4* dst = (float4*)(g_W + (size_t)o * KTOT + (size_t)blockIdx.y * (256 * NFEAT));
    if (tid < 224) dst[tid] = ((const float4*)sbuf)[tid];
}

// ---------------------------------------------------------------------------
// Kernel 2: features (silu + closed-form uniform cubic B-spline) -> fp16 [b][k]
// ---------------------------------------------------------------------------
__global__ void kan_features(const float* __restrict__ x) {
    __shared__ __half sbuf[256 * NFEAT];
    int b = blockIdx.x;
    int tid = threadIdx.x;
    int i = blockIdx.y * 256 + tid;
    float xv = x[(size_t)b * IN_F + i];

    float e   = __expf(-xv);
    float sil = xv * __fdividef(1.0f, 1.0f + e);

    float u  = (xv + 1.0f) * 1.5f;
    int idx  = (int)floorf(u);
    idx = idx < 0 ? 0 : (idx > 2 ? 2 : idx);
    float t  = u - (float)idx;
    float t2 = t * t, t3 = t2 * t;
    float omt = 1.0f - t;
    const float c6 = 1.0f / 6.0f;
    float v0 = omt * omt * omt * c6;
    float v1 = (3.0f * t3 - 6.0f * t2 + 4.0f) * c6;
    float v2 = (-3.0f * t3 + 3.0f * t2 + 3.0f * t + 1.0f) * c6;
    float v3 = t3 * c6;

    float vals[NFEAT];
    vals[0] = sil;
    vals[1] = (idx == 0) ? v0 : 0.0f;
    vals[2] = (idx == 0) ? v1 : ((idx == 1) ? v0 : 0.0f);
    vals[3] = (idx == 0) ? v2 : ((idx == 1) ? v1 : v0);
    vals[4] = (idx == 0) ? v3 : ((idx == 1) ? v2 : v1);
    vals[5] = (idx == 1) ? v3 : ((idx == 2) ? v2 : 0.0f);
    vals[6] = (idx == 2) ? v3 : 0.0f;

#pragma unroll
    for (int j = 0; j < NFEAT; j++)
        sbuf[tid * NFEAT + j] = __float2half_rn(vals[j]);
    __syncthreads();
    float4* dst = (float4*)(g_A + (size_t)b * KTOT + (size_t)blockIdx.y * (256 * NFEAT));
    if (tid < 224) dst[tid] = ((const float4*)sbuf)[tid];
}

// ---------------------------------------------------------------------------
// Kernel 3: fp16 mma.sync m16n8k16 GEMM  C[b,o] = sum_k A[b][k] * W[o][k]
// CTA 128x256, BK=64 halves (128B data/row, 144B stride -> conflict-free lds32:
// bank(row q, lane cl) = (36q+cl) mod 32 = 4q+cl, perfect 32-bank cover),
// 256 threads (8 warps, warp tile 64x64), 3-stage cp.async ring.
// ---------------------------------------------------------------------------
#define BM 128
#define BN 256
#define BK 64
#define NT (KTOT / BK)          // 112
#define ROWB 144                // bytes per smem row (128 data + 16 pad)
#define A_STG_B (BM * ROWB)     // 18432
#define B_STG_B (BN * ROWB)     // 36864
#define STG_B (A_STG_B + B_STG_B)
#define NSTAGE 3
#define SMEM_TOTAL (NSTAGE * STG_B)   // 165888

__device__ __forceinline__ void load_stage(uint32_t sb, int bm0, int bn0,
                                           int t, int stg, int tid) {
    uint32_t base = sb + stg * STG_B;
    int k0 = t * BK;
    // A: 128 rows x 8 chunks of 16B (8 halves)
#pragma unroll
    for (int r = 0; r < 4; r++) {
        int c = tid + r * 256;
        int row = c >> 3, ch = c & 7;
        CP_ASYNC16(base + (uint32_t)(row * ROWB + ch * 16),
                   g_A + (size_t)(bm0 + row) * KTOT + k0 + ch * 8);
    }
    uint32_t bbase = base + A_STG_B;
#pragma unroll
    for (int r = 0; r < 8; r++) {
        int c = tid + r * 256;
        int row = c >> 3, ch = c & 7;
        CP_ASYNC16(bbase + (uint32_t)(row * ROWB + ch * 16),
                   g_W + (size_t)(bn0 + row) * KTOT + k0 + ch * 8);
    }
    CP_COMMIT();
}

__global__ __launch_bounds__(256, 1) void kan_gemm(float* __restrict__ C) {
    extern __shared__ char dsm[];
    uint32_t sb = smem_u32(dsm);
    const int tid = threadIdx.x;
    const int wid = tid >> 5, lane = tid & 31;
    const int q = lane >> 2, cl = lane & 3;
    const int bm0 = blockIdx.y * BM;   // y = bm (slow)
    const int bn0 = blockIdx.x * BN;   // x = bn (fast): consecutive CTAs share A
    const int m0 = (wid & 1) * 64;
    const int n0 = (wid >> 1) * 64;

    float d[4][8][4];
#pragma unroll
    for (int mb = 0; mb < 4; mb++)
#pragma unroll
        for (int nb = 0; nb < 8; nb++)
#pragma unroll
            for (int r = 0; r < 4; r++) d[mb][nb][r] = 0.0f;

    load_stage(sb, bm0, bn0, 0, 0, tid);
    load_stage(sb, bm0, bn0, 1, 1, tid);

    // per-thread fragment base offsets (within a stage)
    const uint32_t afoff = (uint32_t)((m0 + q) * ROWB + 4 * cl);
    const uint32_t bfoff = (uint32_t)(A_STG_B + (n0 + q) * ROWB + 4 * cl);

    for (int t = 0; t < NT; t++) {
        const int stg = t % NSTAGE;
        CP_WAIT(1);
        __syncthreads();
        if (t + 2 < NT) load_stage(sb, bm0, bn0, t + 2, (t + 2) % NSTAGE, tid);

        const uint32_t stbase = sb + stg * STG_B;
        const uint32_t abase = stbase + afoff;
        const uint32_t bbase = stbase + bfoff;

#pragma unroll
        for (int kk = 0; kk < 4; kk++) {   // 4 x k16 per BK=64
            const uint32_t ko = (uint32_t)(kk * 32);
            uint32_t a[4][4];
#pragma unroll
            for (int mb = 0; mb < 4; mb++) {
                uint32_t aa = abase + (uint32_t)(mb * 16 * ROWB) + ko;
                a[mb][0] = lds32(aa);                 // row q,   k pair 2cl
                a[mb][1] = lds32(aa + 8 * ROWB);      // row q+8, k pair 2cl
                a[mb][2] = lds32(aa + 16);            // row q,   k pair 2cl+8
                a[mb][3] = lds32(aa + 8 * ROWB + 16); // row q+8, k pair 2cl+8
            }
            uint32_t b[8][2];
#pragma unroll
            for (int nb = 0; nb < 8; nb++) {
                uint32_t ba = bbase + (uint32_t)(nb * 8 * ROWB) + ko;
                b[nb][0] = lds32(ba);
                b[nb][1] = lds32(ba + 16);
            }
#pragma unroll
            for (int mb = 0; mb < 4; mb++)
#pragma unroll
                for (int nb = 0; nb < 8; nb++)
                    MMA_F16(d[mb][nb], a[mb][0], a[mb][1], a[mb][2], a[mb][3],
                            b[nb][0], b[nb][1]);
        }
    }

    // epilogue: each 4-lane group writes contiguous float2 runs
#pragma unroll
    for (int mb = 0; mb < 4; mb++) {
        int row0 = bm0 + m0 + mb * 16 + q;
#pragma unroll
        for (int nb = 0; nb < 8; nb++) {
            int col = bn0 + n0 + nb * 8 + 2 * cl;
            float2* p0 = (float2*)(C + (size_t)row0 * OUT_F + col);
            *p0 = make_float2(d[mb][nb][0], d[mb][nb][1]);
            float2* p1 = (float2*)(C + (size_t)(row0 + 8) * OUT_F + col);
            *p1 = make_float2(d[mb][nb][2], d[mb][nb][3]);
        }
    }
}

// ---------------------------------------------------------------------------
// Launch. Inputs: x, base_weight, spline_weight, spline_scaler, grid
// ---------------------------------------------------------------------------
extern "C" void kernel_launch(void* const* d_in, const int* in_sizes, int n_in,
                              void* d_out, int out_size) {
    (void)in_sizes; (void)n_in; (void)out_size;
    const float* x  = (const float*)d_in[0];
    const float* bw = (const float*)d_in[1];
    const float* sw = (const float*)d_in[2];
    const float* sc = (const float*)d_in[3];
    float* out = (float*)d_out;

    cudaFuncSetAttribute(kan_gemm, cudaFuncAttributeMaxDynamicSharedMemorySize,
                         SMEM_TOTAL);

    kan_prep_w<<<dim3(OUT_F, IN_F / 256), 256>>>(bw, sw, sc);
    kan_features<<<dim3(BATCH, IN_F / 256), 256>>>(x);
    kan_gemm<<<dim3(OUT_F / BN, BATCH / BM), 256, SMEM_TOTAL>>>(out);
}

// round 9
// speedup vs baseline: 5.6346x; 1.0079x over previous
#include <cuda_runtime.h>
#include <cuda_fp16.h>
#include <cstdint>
#include <cstddef>

#define IN_F   1024
#define OUT_F  1024
#define BATCH  8192
#define NFEAT  7
#define KTOT   (IN_F * NFEAT)   // 7168

// ---------------------------------------------------------------------------
// Scratch: fp16 operands (fp32 accumulate in the MMA).
// g_A: [b][k] row-major. g_W: [o][k].
// ---------------------------------------------------------------------------
__device__ __align__(256) __half g_A[(size_t)BATCH * KTOT];
__device__ __align__(256) __half g_W[(size_t)OUT_F * KTOT];

// ---------------------------------------------------------------------------
// Helpers
// ---------------------------------------------------------------------------
__device__ __forceinline__ unsigned smem_u32(const void* p) {
    return (unsigned)__cvta_generic_to_shared(p);
}
#define CP_ASYNC16(dst_u32, src_ptr) \
    asm volatile("cp.async.cg.shared.global [%0], [%1], 16;\n" :: "r"(dst_u32), "l"(src_ptr))
#define CP_COMMIT() asm volatile("cp.async.commit_group;\n")
#define CP_WAIT(n)  asm volatile("cp.async.wait_group %0;\n" :: "n"(n))

#define LDSM_X4(r0, r1, r2, r3, addr) \
    asm volatile("ldmatrix.sync.aligned.m8n8.x4.shared.b16 {%0,%1,%2,%3}, [%4];" \
                 : "=r"(r0), "=r"(r1), "=r"(r2), "=r"(r3) : "r"(addr))

#define MMA_F16(d, a0, a1, a2, a3, b0, b1) \
    asm volatile( \
        "mma.sync.aligned.m16n8k16.row.col.f32.f16.f16.f32 " \
        "{%0,%1,%2,%3}, {%4,%5,%6,%7}, {%8,%9}, {%0,%1,%2,%3};" \
        : "+f"((d)[0]), "+f"((d)[1]), "+f"((d)[2]), "+f"((d)[3]) \
        : "r"(a0), "r"(a1), "r"(a2), "r"(a3), "r"(b0), "r"(b1))

// ---------------------------------------------------------------------------
// Kernel 1: combined weights -> fp16, layout [o][k]
// ---------------------------------------------------------------------------
__global__ void kan_prep_w(const float* __restrict__ bw,
                           const float* __restrict__ sw,
                           const float* __restrict__ sc) {
    __shared__ __half sbuf[256 * NFEAT];
    int o = blockIdx.x;
    int tid = threadIdx.x;
    int i = blockIdx.y * 256 + tid;
    size_t oi = (size_t)o * IN_F + i;
    float s = sc[oi];
    float vals[NFEAT];
    vals[0] = bw[oi];
    const float* swp = sw + oi * 6;
#pragma unroll
    for (int n = 0; n < 6; n++) vals[n + 1] = swp[n] * s;
#pragma unroll
    for (int j = 0; j < NFEAT; j++)
        sbuf[tid * NFEAT + j] = __float2half_rn(vals[j]);
    __syncthreads();
    float4* dst = (float4*)(g_W + (size_t)o * KTOT + (size_t)blockIdx.y * (256 * NFEAT));
    if (tid < 224) dst[tid] = ((const float4*)sbuf)[tid];
}

// ---------------------------------------------------------------------------
// Kernel 2: features (silu + closed-form uniform cubic B-spline) -> fp16 [b][k]
// ---------------------------------------------------------------------------
__global__ void kan_features(const float* __restrict__ x) {
    __shared__ __half sbuf[256 * NFEAT];
    int b = blockIdx.x;
    int tid = threadIdx.x;
    int i = blockIdx.y * 256 + tid;
    float xv = x[(size_t)b * IN_F + i];

    float e   = __expf(-xv);
    float sil = xv * __fdividef(1.0f, 1.0f + e);

    float u  = (xv + 1.0f) * 1.5f;
    int idx  = (int)floorf(u);
    idx = idx < 0 ? 0 : (idx > 2 ? 2 : idx);
    float t  = u - (float)idx;
    float t2 = t * t, t3 = t2 * t;
    float omt = 1.0f - t;
    const float c6 = 1.0f / 6.0f;
    float v0 = omt * omt * omt * c6;
    float v1 = (3.0f * t3 - 6.0f * t2 + 4.0f) * c6;
    float v2 = (-3.0f * t3 + 3.0f * t2 + 3.0f * t + 1.0f) * c6;
    float v3 = t3 * c6;

    float vals[NFEAT];
    vals[0] = sil;
    vals[1] = (idx == 0) ? v0 : 0.0f;
    vals[2] = (idx == 0) ? v1 : ((idx == 1) ? v0 : 0.0f);
    vals[3] = (idx == 0) ? v2 : ((idx == 1) ? v1 : v0);
    vals[4] = (idx == 0) ? v3 : ((idx == 1) ? v2 : v1);
    vals[5] = (idx == 1) ? v3 : ((idx == 2) ? v2 : 0.0f);
    vals[6] = (idx == 2) ? v3 : 0.0f;

#pragma unroll
    for (int j = 0; j < NFEAT; j++)
        sbuf[tid * NFEAT + j] = __float2half_rn(vals[j]);
    __syncthreads();
    float4* dst = (float4*)(g_A + (size_t)b * KTOT + (size_t)blockIdx.y * (256 * NFEAT));
    if (tid < 224) dst[tid] = ((const float4*)sbuf)[tid];
}

// ---------------------------------------------------------------------------
// Kernel 3: fp16 mma.sync m16n8k16 GEMM  C[b,o] = sum_k A[b][k] * W[o][k]
// CTA 128x256, BK=64 halves, 144B smem row stride (LDSM phases hit banks
// 4r..4r+3, all 32 banks, conflict-free), 8 warps (warp tile 64x64),
// 3-stage cp.async ring, ldmatrix.x4 fragment loads, register double-buffer.
// ---------------------------------------------------------------------------
#define BM 128
#define BN 256
#define BK 64
#define NT (KTOT / BK)          // 112
#define ROWB 144                // bytes per smem row (128 data + 16 pad)
#define A_STG_B (BM * ROWB)     // 18432
#define B_STG_B (BN * ROWB)     // 36864
#define STG_B (A_STG_B + B_STG_B)
#define NSTAGE 3
#define SMEM_TOTAL (NSTAGE * STG_B)   // 165888

__device__ __forceinline__ void load_stage(uint32_t sb, int bm0, int bn0,
                                           int t, int stg, int tid) {
    uint32_t base = sb + stg * STG_B;
    int k0 = t * BK;
#pragma unroll
    for (int r = 0; r < 4; r++) {
        int c = tid + r * 256;
        int row = c >> 3, ch = c & 7;
        CP_ASYNC16(base + (uint32_t)(row * ROWB + ch * 16),
                   g_A + (size_t)(bm0 + row) * KTOT + k0 + ch * 8);
    }
    uint32_t bbase = base + A_STG_B;
#pragma unroll
    for (int r = 0; r < 8; r++) {
        int c = tid + r * 256;
        int row = c >> 3, ch = c & 7;
        CP_ASYNC16(bbase + (uint32_t)(row * ROWB + ch * 16),
                   g_W + (size_t)(bn0 + row) * KTOT + k0 + ch * 8);
    }
    CP_COMMIT();
}

struct Frag {
    uint32_t a[4][4];
    uint32_t b[8][2];
};

// abase/bbase: per-thread LDSM lane addresses for kk=0 of the current stage
__device__ __forceinline__ void load_frag(Frag& f, uint32_t abase, uint32_t bbase,
                                          int kk) {
    const uint32_t ko = (uint32_t)(kk * 32);
#pragma unroll
    for (int mb = 0; mb < 4; mb++)
        LDSM_X4(f.a[mb][0], f.a[mb][1], f.a[mb][2], f.a[mb][3],
                abase + (uint32_t)(mb * 16 * ROWB) + ko);
#pragma unroll
    for (int n2 = 0; n2 < 4; n2++)
        LDSM_X4(f.b[2 * n2][0], f.b[2 * n2][1], f.b[2 * n2 + 1][0], f.b[2 * n2 + 1][1],
                bbase + (uint32_t)(n2 * 16 * ROWB) + ko);
}

__global__ __launch_bounds__(256, 1) void kan_gemm(float* __restrict__ C) {
    extern __shared__ char dsm[];
    uint32_t sb = smem_u32(dsm);
    const int tid = threadIdx.x;
    const int wid = tid >> 5, lane = tid & 31;
    const int q = lane >> 2, cl = lane & 3;
    const int bm0 = blockIdx.y * BM;   // y = bm (slow)
    const int bn0 = blockIdx.x * BN;   // x = bn (fast): consecutive CTAs share A
    const int m0 = (wid & 1) * 64;
    const int n0 = (wid >> 1) * 64;

    float d[4][8][4];
#pragma unroll
    for (int mb = 0; mb < 4; mb++)
#pragma unroll
        for (int nb = 0; nb < 8; nb++)
#pragma unroll
            for (int r = 0; r < 4; r++) d[mb][nb][r] = 0.0f;

    load_stage(sb, bm0, bn0, 0, 0, tid);
    load_stage(sb, bm0, bn0, 1, 1, tid);

    // LDSM lane addressing: r8 = row-in-tile, tq = tile index (0..3).
    // A tiles: (rowblk0,k0),(rowblk1,k0),(rowblk0,k8),(rowblk1,k8)
    // B tiles: (nblk0,k0),(nblk0,k8),(nblk1,k0),(nblk1,k8)
    const int r8 = lane & 7, tq = lane >> 3;
    const uint32_t afoff =
        (uint32_t)((m0 + (tq & 1) * 8 + r8) * ROWB + (tq >> 1) * 16);
    const uint32_t bfoff =
        (uint32_t)(A_STG_B + (n0 + (tq >> 1) * 8 + r8) * ROWB + (tq & 1) * 16);

    Frag fr[2];
    for (int t = 0; t < NT; t++) {
        const int stg = t % NSTAGE;
        CP_WAIT(1);
        __syncthreads();
        if (t + 2 < NT) load_stage(sb, bm0, bn0, t + 2, (t + 2) % NSTAGE, tid);

        const uint32_t stbase = sb + stg * STG_B;
        const uint32_t abase = stbase + afoff;
        const uint32_t bbase = stbase + bfoff;

        load_frag(fr[0], abase, bbase, 0);
#pragma unroll
        for (int kk = 0; kk < 4; kk++) {
            if (kk < 3) load_frag(fr[(kk + 1) & 1], abase, bbase, kk + 1);
            Frag& f = fr[kk & 1];
#pragma unroll
            for (int mb = 0; mb < 4; mb++)
#pragma unroll
                for (int nb = 0; nb < 8; nb++)
                    MMA_F16(d[mb][nb], f.a[mb][0], f.a[mb][1], f.a[mb][2], f.a[mb][3],
                            f.b[nb][0], f.b[nb][1]);
        }
    }

    // epilogue: each 4-lane group writes contiguous float2 runs
#pragma unroll
    for (int mb = 0; mb < 4; mb++) {
        int row0 = bm0 + m0 + mb * 16 + q;
#pragma unroll
        for (int nb = 0; nb < 8; nb++) {
            int col = bn0 + n0 + nb * 8 + 2 * cl;
            float2* p0 = (float2*)(C + (size_t)row0 * OUT_F + col);
            *p0 = make_float2(d[mb][nb][0], d[mb][nb][1]);
            float2* p1 = (float2*)(C + (size_t)(row0 + 8) * OUT_F + col);
            *p1 = make_float2(d[mb][nb][2], d[mb][nb][3]);
        }
    }
}

// ---------------------------------------------------------------------------
// Launch. Inputs: x, base_weight, spline_weight, spline_scaler, grid
// ---------------------------------------------------------------------------
extern "C" void kernel_launch(void* const* d_in, const int* in_sizes, int n_in,
                              void* d_out, int out_size) {
    (void)in_sizes; (void)n_in; (void)out_size;
    const float* x  = (const float*)d_in[0];
    const float* bw = (const float*)d_in[1];
    const float* sw = (const float*)d_in[2];
    const float* sc = (const float*)d_in[3];
    float* out = (float*)d_out;

    cudaFuncSetAttribute(kan_gemm, cudaFuncAttributeMaxDynamicSharedMemorySize,
                         SMEM_TOTAL);

    kan_prep_w<<<dim3(OUT_F, IN_F / 256), 256>>>(bw, sw, sc);
    kan_features<<<dim3(BATCH, IN_F / 256), 256>>>(x);
    kan_gemm<<<dim3(OUT_F / BN, BATCH / BM), 256, SMEM_TOTAL>>>(out);
}